// round 17
// baseline (speedup 1.0000x reference)
#include <cuda_runtime.h>
#include <math.h>

// ---------------------------------------------------------------------------
// ConvLSTM stack, R15: R13 (skewed pipeline + FFMA2 + fast_tanh + PDL) with
// the L1 layer rewritten as tf32 mma.sync implicit GEMM:
//   gates[512px x 16] = A[512 x 63(im2col)] x W[63 x 16]   (fp32 accum)
// m16n8k8 fragments; accumulators staged via per-warp smem gates buffer;
// LSTM epilogue + fused maxpool unchanged in math. L2-L4 identical to R13.
// ---------------------------------------------------------------------------

static constexpr int Bv = 32;
static constexpr int Tv = 24;

__device__ float g_hs1[(size_t)Bv*Tv*126*126*4];
__device__ float g_c1 [(size_t)Bv*126*126*4];
__device__ float g_p1 [(size_t)Bv*Tv*63*63*4];
__device__ float g_hs2[(size_t)Bv*Tv*61*61*8];
__device__ float g_c2 [(size_t)Bv*61*61*8];
__device__ float g_p2 [(size_t)Bv*Tv*31*31*8];
__device__ float g_hs3[(size_t)Bv*Tv*29*29*12];
__device__ float g_c3 [(size_t)Bv*29*29*12];
__device__ float g_p3 [(size_t)Bv*Tv*15*15*12];
__device__ float g_hs4[(size_t)Bv*Tv*13*13*16];
__device__ float g_c4 [(size_t)Bv*13*13*16];
__device__ float g_p4 [(size_t)Bv*Tv*7*7*16];
__device__ float g_logits[Bv*50];

__device__ __forceinline__ float hsig(float x) { return __saturatef(0.2f * x + 0.5f); }

__device__ __forceinline__ float fast_tanh(float x) {
    float xc = fminf(fmaxf(x, -9.0f), 9.0f);
    float t = __expf(2.0f * xc);
    return __fdividef(t - 1.0f, t + 1.0f);
}

__device__ __forceinline__ unsigned long long pack2(float v) {
    unsigned long long r;
    asm("mov.b64 %0, {%1, %1};" : "=l"(r) : "f"(v));
    return r;
}
__device__ __forceinline__ void ffma2(unsigned long long& d, unsigned long long a,
                                      unsigned long long b) {
    asm("fma.rn.f32x2 %0, %1, %2, %0;" : "+l"(d) : "l"(a), "l"(b));
}

// tf32 round (RNA) keeping fp32 container.
__device__ __forceinline__ float tf32r(float v) {
    unsigned r;
    asm("cvt.rna.tf32.f32 %0, %1;" : "=r"(r) : "f"(v));
    return __uint_as_float(r);
}

__device__ __forceinline__ void mma16n8k8(float* acc, unsigned a0, unsigned a1,
                                          unsigned a2, unsigned a3,
                                          unsigned b0, unsigned b1) {
    asm volatile(
        "mma.sync.aligned.m16n8k8.row.col.f32.tf32.tf32.f32 "
        "{%0,%1,%2,%3}, {%4,%5,%6,%7}, {%8,%9}, {%0,%1,%2,%3};"
        : "+f"(acc[0]), "+f"(acc[1]), "+f"(acc[2]), "+f"(acc[3])
        : "r"(a0), "r"(a1), "r"(a2), "r"(a3), "r"(b0), "r"(b1));
}

static constexpr int SMEM_RAW = 38400;

// =====================  L1: tf32 mma implicit-GEMM path  =====================
// Tile 32x16 px, 512 px/block, K=64 (27 in-taps + 36 rec-taps + 1 zero pad),
// N=16 gates. Per warp: 4 m16 tiles, each 8 ksteps x 2 n8 tiles.
__device__ __forceinline__ void lstm1_mma(
    char* raw, int bid,
    const float* __restrict__ x,
    const float* __restrict__ Wx, const float* __restrict__ Wh,
    const float* __restrict__ bias,
    float* __restrict__ hs, float* __restrict__ c_buf,
    float* __restrict__ pool_out, int t)
{
    constexpr int TX = 32, TY = 16, TXP = 34, TYP = 18;
    constexpr int HIN = 128, WIN = 128, HO = 126, WO = 126;
    constexpr int HOp = 63, WOp = 63, F = 4;
    constexpr int NXT = 4, NYT = 8;
    constexpr int NTHR = 256;

    float* s_in  = reinterpret_cast<float*>(raw);        // 3*18*34 = 1836
    float* s_h   = s_in + 3 * TYP * TXP;                 // 4*18*34 = 2448
    float* s_wk  = s_h + 4 * TYP * TXP;                  // 64*16   = 1024
    unsigned* s_lut = reinterpret_cast<unsigned*>(s_wk + 64 * 16);   // 64
    float* s_gb  = reinterpret_cast<float*>(s_lut + 64); // 8 warps * 256
    float* s_pool = s_gb + 8 * 256;                      // 4*16*32 = 2048
    float* rawf = s_in;

    int r = bid;
    const int xT = r % NXT; r /= NXT;
    const int yT = r % NYT; const int b = r / NYT;
    const int x0 = xT * TX, y0 = yT * TY;
    const int tid = threadIdx.x;

    // ---- weights (tf32-rounded), k-ordered: 27 input taps then 36 rec ----
    for (int i = tid; i < 64 * 16; i += NTHR) {
        int k = i >> 4, n = i & 15;
        float v = (k < 27) ? Wx[k * 16 + n] : ((k < 63) ? Wh[(k - 27) * 16 + n] : 0.0f);
        s_wk[i] = tf32r(v);
    }
    // ---- A-address LUT: word offset of (tap,ci) plane base within raw ----
    if (tid < 64) {
        int k = tid; unsigned off;
        if (k < 27)      { int tap = k / 3, ci = k % 3; off = ci * TYP * TXP + (tap / 3) * TXP + (tap % 3); }
        else if (k < 63) { int kk = k - 27; int tap = kk / 4, ci = kk % 4;
                           off = 3 * TYP * TXP + ci * TYP * TXP + (tap / 3) * TXP + (tap % 3); }
        else off = 0;   // pad column: weight is zero
        s_lut[k] = off;
    }
    // ---- input tile (const input x -> before PDL sync), tf32-rounded ----
    {
        const float* xin = x + ((size_t)(b * Tv + t)) * HIN * WIN * 3;
        for (int i = tid; i < TYP * TXP * 3; i += NTHR) {
            int ci = i % 3; int rr = i / 3;
            int xx = rr % TXP; int yy = rr / TXP;
            int gy = y0 + yy, gx = x0 + xx;
            float v = (gy < HIN && gx < WIN) ? __ldg(&xin[((size_t)gy * WIN + gx) * 3 + ci]) : 0.0f;
            s_in[(ci * TYP + yy) * TXP + xx] = tf32r(v);
        }
    }

    cudaGridDependencySynchronize();

    // ---- h_{t-1} tile (zero at t==0), tf32-rounded ----
    if (t > 0) {
        const float* hp = hs + ((size_t)(b * Tv + (t - 1))) * HO * WO * F;
        for (int i = tid; i < TYP * TXP * F; i += NTHR) {
            int ci = i % F; int rr = i / F;
            int xx = rr % TXP; int yy = rr / TXP;
            int hr = y0 - 1 + yy, hc = x0 - 1 + xx;
            float v = (hr >= 0 && hr < HO && hc >= 0 && hc < WO)
                        ? __ldg(&hp[((size_t)hr * WO + hc) * F + ci]) : 0.0f;
            s_h[(ci * TYP + yy) * TXP + xx] = tf32r(v);
        }
    } else {
        for (int i = tid; i < TYP * TXP * F; i += NTHR) s_h[i] = 0.0f;
    }
    __syncthreads();

    const int lane = tid & 31, w = tid >> 5;
    const int g = lane >> 2, tau = lane & 3;
    float* gb = s_gb + w * 256;

    const float bi00 = __ldg(&bias[2 * tau]),     bi01 = __ldg(&bias[2 * tau + 1]);
    const float bi10 = __ldg(&bias[8 + 2 * tau]), bi11 = __ldg(&bias[8 + 2 * tau + 1]);

    #pragma unroll
    for (int i = 0; i < 4; i++) {
        const int mt = w * 4 + i;
        const int base = mt * 16;
        const int r1 = base + g, r2 = r1 + 8;
        const unsigned off1 = (unsigned)((r1 >> 5) * TXP + (r1 & 31));
        const unsigned off2 = (unsigned)((r2 >> 5) * TXP + (r2 & 31));

        float acc0[4] = {bi00, bi01, bi00, bi01};
        float acc1[4] = {bi10, bi11, bi10, bi11};

        #pragma unroll
        for (int ks = 0; ks < 8; ks++) {
            unsigned l1 = s_lut[ks * 8 + tau];
            unsigned l2 = s_lut[ks * 8 + tau + 4];
            unsigned a0 = __float_as_uint(rawf[l1 + off1]);
            unsigned a1 = __float_as_uint(rawf[l1 + off2]);
            unsigned a2 = __float_as_uint(rawf[l2 + off1]);
            unsigned a3 = __float_as_uint(rawf[l2 + off2]);
            unsigned b00 = __float_as_uint(s_wk[(ks * 8 + tau) * 16 + g]);
            unsigned b01 = __float_as_uint(s_wk[(ks * 8 + tau + 4) * 16 + g]);
            mma16n8k8(acc0, a0, a1, a2, a3, b00, b01);
            unsigned b10 = __float_as_uint(s_wk[(ks * 8 + tau) * 16 + 8 + g]);
            unsigned b11 = __float_as_uint(s_wk[(ks * 8 + tau + 4) * 16 + 8 + g]);
            mma16n8k8(acc1, a0, a1, a2, a3, b10, b11);
        }

        // Stage gates: gb[row][col], row=px-in-tile, col=gate 0..15
        gb[g * 16 + 2 * tau]            = acc0[0];
        gb[g * 16 + 2 * tau + 1]        = acc0[1];
        gb[(g + 8) * 16 + 2 * tau]      = acc0[2];
        gb[(g + 8) * 16 + 2 * tau + 1]  = acc0[3];
        gb[g * 16 + 8 + 2 * tau]        = acc1[0];
        gb[g * 16 + 8 + 2 * tau + 1]    = acc1[1];
        gb[(g + 8) * 16 + 8 + 2 * tau]  = acc1[2];
        gb[(g + 8) * 16 + 8 + 2 * tau + 1] = acc1[3];
        __syncwarp();

        // LSTM epilogue for these 16 px: 64 (px,ch) units over 32 lanes
        #pragma unroll
        for (int u = 0; u < 2; u++) {
            int unit = u * 32 + lane;
            int px = unit >> 2, ch = unit & 3;
            int pxg = base + px;
            int py = pxg >> 5, lx2 = pxg & 31;
            int gy = y0 + py, gx = x0 + lx2;
            bool valid = (gy < HO) && (gx < WO);
            float hnv = -INFINITY;
            if (valid) {
                float iv = gb[px * 16 + ch];
                float fv = gb[px * 16 + 4 + ch];
                float cv = gb[px * 16 + 8 + ch];
                float ov = gb[px * 16 + 12 + ch];
                size_t pix = (size_t)b * HO * WO + (size_t)gy * WO + gx;
                float cold = (t > 0) ? c_buf[pix * F + ch] : 0.0f;
                float cn = hsig(fv) * cold + hsig(iv) * fast_tanh(cv);
                c_buf[pix * F + ch] = cn;
                hnv = hsig(ov) * fast_tanh(cn);
                hs[(((size_t)(b * Tv + t) * HO + gy) * WO + gx) * F + ch] = hnv;
            }
            s_pool[(ch * 16 + py) * TX + lx2] = hnv;
        }
        __syncwarp();
    }
    __syncthreads();

    // ---- fused 2x2 maxpool (SAME) on the staged tile ----
    {
        constexpr int TXH = TX / 2, TYH = TY / 2;
        for (int i = tid; i < F * TYH * TXH; i += NTHR) {
            int f = i % F; int rr = i / F;
            int oxc = rr % TXH, oyc = rr / TXH;
            int oy = (y0 >> 1) + oyc, ox = (x0 >> 1) + oxc;
            if (oy < HOp && ox < WOp) {
                int r0 = 2 * oyc, rr1 = r0 + 1, q0 = 2 * oxc, q1 = q0 + 1;
                float m = fmaxf(s_pool[(f * 16 + r0) * TX + q0],
                                s_pool[(f * 16 + r0) * TX + q1]);
                m = fmaxf(m, fmaxf(s_pool[(f * 16 + rr1) * TX + q0],
                                   s_pool[(f * 16 + rr1) * TX + q1]));
                pool_out[(((size_t)(b * Tv + t) * HOp + oy) * WOp + ox) * F + f] = m;
            }
        }
    }
}

// =====================  L2-L4: scalar FFMA2 path (R13)  =====================
template<int CIN, int F, int FT, int HIN, int WIN, int TX, int TY, bool IN_DEP>
__device__ __forceinline__ void lstm_impl(
    char* raw, int bid,
    const float* __restrict__ in_seq,
    const float* __restrict__ Wx,
    const float* __restrict__ Wh,
    const float* __restrict__ bias,
    float* __restrict__ hs,
    float* __restrict__ c_buf,
    float* __restrict__ pool_out,
    int t)
{
    constexpr int NTHR = 256;
    constexpr int BY = NTHR / TX;
    constexpr int PY = (TY + BY - 1) / BY;
    constexpr int BYP = BY * PY;
    constexpr int G4 = 4 * FT;
    constexpr int NQ = G4 / 2;
    constexpr int NH = NQ / 4;
    constexpr int HO = HIN - 2, WO = WIN - 2;
    constexpr int HOp = (HO + 1) / 2, WOp = (WO + 1) / 2;
    constexpr int C4 = 4 * F;
    constexpr int TXP = TX + 2, TYP = TY + 2;
    constexpr int NXT = (WO + TX - 1) / TX;
    constexpr int NYT = (HO + TY - 1) / TY;
    constexpr int NG = F / FT;

    float* s_in = reinterpret_cast<float*>(raw);
    float* s_h  = s_in + CIN * TYP * TXP;
    float* s_wx = s_h  + F * TYP * TXP;
    float* s_wh = s_wx + 9 * CIN * G4;
    float* s_pool = s_h;

    int r = bid;
    const int g  = r % NG;  r /= NG;
    const int xT = r % NXT; r /= NXT;
    const int yT = r % NYT; const int b = r / NYT;
    const int x0 = xT * TX, y0 = yT * TY;
    const int f0 = g * FT;
    const int tid = threadIdx.x;
    const int lx = tid % TX, ly = tid / TX;

    for (int i = tid; i < 9 * CIN * G4; i += NTHR) {
        int col = i % G4, rc = i / G4;
        s_wx[i] = Wx[rc * C4 + (col / FT) * F + f0 + (col % FT)];
    }
    for (int i = tid; i < 9 * F * G4; i += NTHR) {
        int col = i % G4, rc = i / G4;
        s_wh[i] = Wh[rc * C4 + (col / FT) * F + f0 + (col % FT)];
    }

    if (IN_DEP) cudaGridDependencySynchronize();

    {
        const float* xin = in_seq + ((size_t)(b * Tv + t)) * HIN * WIN * CIN;
        for (int i = tid; i < TYP * TXP * CIN; i += NTHR) {
            int ci = i % CIN; int rr = i / CIN;
            int xx = rr % TXP; int yy = rr / TXP;
            int gy = y0 + yy, gx = x0 + xx;
            float v = (gy < HIN && gx < WIN) ? __ldg(&xin[((size_t)gy * WIN + gx) * CIN + ci]) : 0.0f;
            s_in[(ci * TYP + yy) * TXP + xx] = v;
        }
    }

    if (!IN_DEP) cudaGridDependencySynchronize();

    if (t > 0) {
        const float* hp = hs + ((size_t)(b * Tv + (t - 1))) * HO * WO * F;
        for (int i = tid; i < TYP * TXP * F; i += NTHR) {
            int ci = i % F; int rr = i / F;
            int xx = rr % TXP; int yy = rr / TXP;
            int hr = y0 - 1 + yy, hc = x0 - 1 + xx;
            float v = (hr >= 0 && hr < HO && hc >= 0 && hc < WO)
                        ? __ldg(&hp[((size_t)hr * WO + hc) * F + ci]) : 0.0f;
            s_h[(ci * TYP + yy) * TXP + xx] = v;
        }
    }
    __syncthreads();

    int ry[PY], rcl[PY];
    #pragma unroll
    for (int p = 0; p < PY; p++) {
        ry[p] = ly + p * BY;
        rcl[p] = (ry[p] < TY) ? ry[p] : (TY - 1);
    }

    unsigned long long acc[PY][NQ];
    {
        #pragma unroll
        for (int q = 0; q < NQ; q++) {
            int m0 = 2 * q, m1 = 2 * q + 1;
            float b0 = __ldg(&bias[(m0 / FT) * F + f0 + (m0 % FT)]);
            float b1 = __ldg(&bias[(m1 / FT) * F + f0 + (m1 % FT)]);
            unsigned long long bp;
            asm("mov.b64 %0, {%1, %2};" : "=l"(bp) : "f"(b0), "f"(b1));
            #pragma unroll
            for (int p = 0; p < PY; p++) acc[p][q] = bp;
        }
    }

    #pragma unroll
    for (int ky = 0; ky < 3; ky++) {
        #pragma unroll
        for (int kx = 0; kx < 3; kx++) {
            #pragma unroll
            for (int ci = 0; ci < CIN; ci++) {
                unsigned long long vv[PY];
                #pragma unroll
                for (int p = 0; p < PY; p++)
                    vv[p] = pack2(s_in[(ci * TYP + rcl[p] + ky) * TXP + lx + kx]);
                const ulonglong2* wq = reinterpret_cast<const ulonglong2*>(
                    s_wx + ((ky * 3 + kx) * CIN + ci) * G4);
                #pragma unroll
                for (int h = 0; h < NH; h++) {
                    ulonglong2 a = wq[2 * h], c = wq[2 * h + 1];
                    #pragma unroll
                    for (int p = 0; p < PY; p++) {
                        ffma2(acc[p][4 * h + 0], vv[p], a.x);
                        ffma2(acc[p][4 * h + 1], vv[p], a.y);
                        ffma2(acc[p][4 * h + 2], vv[p], c.x);
                        ffma2(acc[p][4 * h + 3], vv[p], c.y);
                    }
                }
            }
        }
    }

    if (t > 0) {
        #pragma unroll
        for (int ky = 0; ky < 3; ky++) {
            #pragma unroll
            for (int kx = 0; kx < 3; kx++) {
                #pragma unroll
                for (int ci = 0; ci < F; ci++) {
                    unsigned long long vv[PY];
                    #pragma unroll
                    for (int p = 0; p < PY; p++)
                        vv[p] = pack2(s_h[(ci * TYP + rcl[p] + ky) * TXP + lx + kx]);
                    const ulonglong2* wq = reinterpret_cast<const ulonglong2*>(
                        s_wh + ((ky * 3 + kx) * F + ci) * G4);
                    #pragma unroll
                    for (int h = 0; h < NH; h++) {
                        ulonglong2 a = wq[2 * h], c = wq[2 * h + 1];
                        #pragma unroll
                        for (int p = 0; p < PY; p++) {
                            ffma2(acc[p][4 * h + 0], vv[p], a.x);
                            ffma2(acc[p][4 * h + 1], vv[p], a.y);
                            ffma2(acc[p][4 * h + 2], vv[p], c.x);
                            ffma2(acc[p][4 * h + 3], vv[p], c.y);
                        }
                    }
                }
            }
        }
    }

    __syncthreads();

    #pragma unroll
    for (int p = 0; p < PY; p++) {
        int gy = y0 + ry[p];
        int gx = x0 + lx;
        bool valid = (ry[p] < TY) && (gy < HO) && (gx < WO);
        float hn[FT];
        #pragma unroll
        for (int j = 0; j < FT; j++) hn[j] = -INFINITY;

        if (valid) {
            float va[G4];
            #pragma unroll
            for (int q = 0; q < NQ; q++) {
                unsigned int lo, hi;
                asm("mov.b64 {%0, %1}, %2;" : "=r"(lo), "=r"(hi) : "l"(acc[p][q]));
                va[2 * q]     = __uint_as_float(lo);
                va[2 * q + 1] = __uint_as_float(hi);
            }
            size_t pix = (size_t)b * HO * WO + (size_t)gy * WO + gx;
            float* cp = c_buf + pix * F + f0;
            float* ho = hs + ((size_t)(b * Tv + t)) * HO * WO * F
                           + ((size_t)gy * WO + gx) * F + f0;
            float co[FT];
            if (t > 0) {
                if constexpr (FT == 4) {
                    float4 c4v = *reinterpret_cast<const float4*>(cp);
                    co[0] = c4v.x; co[1] = c4v.y; co[2] = c4v.z; co[3] = c4v.w;
                } else {
                    float2 c2v = *reinterpret_cast<const float2*>(cp);
                    co[0] = c2v.x; co[1] = c2v.y;
                }
            } else {
                #pragma unroll
                for (int j = 0; j < FT; j++) co[j] = 0.0f;
            }
            float cn[FT];
            #pragma unroll
            for (int j = 0; j < FT; j++) {
                float iv = va[j];
                float fv = va[FT + j];
                float cv = va[2 * FT + j];
                float ov = va[3 * FT + j];
                float c2 = hsig(fv) * co[j] + hsig(iv) * fast_tanh(cv);
                cn[j] = c2;
                hn[j] = hsig(ov) * fast_tanh(c2);
            }
            if constexpr (FT == 4) {
                *reinterpret_cast<float4*>(cp) = make_float4(cn[0], cn[1], cn[2], cn[3]);
                *reinterpret_cast<float4*>(ho) = make_float4(hn[0], hn[1], hn[2], hn[3]);
            } else {
                *reinterpret_cast<float2*>(cp) = make_float2(cn[0], cn[1]);
                *reinterpret_cast<float2*>(ho) = make_float2(hn[0], hn[1]);
            }
        }
        #pragma unroll
        for (int j = 0; j < FT; j++)
            s_pool[(j * BYP + ry[p]) * TX + lx] = hn[j];
    }
    __syncthreads();

    {
        constexpr int TXH = TX / 2, TYH = (TY + 1) / 2;
        for (int i = tid; i < FT * TYH * TXH; i += NTHR) {
            int f = i % FT; int rr = i / FT;
            int oxc = rr % TXH, oyc = rr / TXH;
            int oy = (y0 >> 1) + oyc, ox = (x0 >> 1) + oxc;
            if (oy < HOp && ox < WOp) {
                int r0 = 2 * oyc, r1 = r0 + 1, q0 = 2 * oxc, q1 = q0 + 1;
                float m = fmaxf(s_pool[(f * BYP + r0) * TX + q0],
                                s_pool[(f * BYP + r0) * TX + q1]);
                if (r1 < TY)
                    m = fmaxf(m, fmaxf(s_pool[(f * BYP + r1) * TX + q0],
                                       s_pool[(f * BYP + r1) * TX + q1]));
                pool_out[(((size_t)(b * Tv + t) * HOp + oy) * WOp + ox) * F + f0 + f] = m;
            }
        }
    }
}

static constexpr int NB1 = 1024;
static constexpr int NB2 = 512;
static constexpr int NB3 = 768;
static constexpr int NB4 = 256;
static constexpr int NBT = NB1 + NB2 + NB3 + NB4;   // 2560

__global__ void __launch_bounds__(256, 4) mega_step(
    const float* __restrict__ x,
    const float* __restrict__ Wx1, const float* __restrict__ Wh1, const float* __restrict__ b1,
    const float* __restrict__ Wx2, const float* __restrict__ Wh2, const float* __restrict__ b2,
    const float* __restrict__ Wx3, const float* __restrict__ Wh3, const float* __restrict__ b3,
    const float* __restrict__ Wx4, const float* __restrict__ Wh4, const float* __restrict__ b4,
    float* hs1, float* c1, float* p1,
    float* hs2, float* c2, float* p2,
    float* hs3, float* c3, float* p3,
    float* hs4, float* c4, float* p4,
    int t1, int t2, int t3, int t4)
{
    __shared__ __align__(16) char raw[SMEM_RAW];
    const int bid = blockIdx.x;
    if (bid < NB1) {
        if (t1 >= 0)
            lstm1_mma(raw, bid, x, Wx1, Wh1, b1, hs1, c1, p1, t1);
    } else if (bid < NB1 + NB2) {
        if (t2 >= 0)
            lstm_impl<4, 8, 4, 63, 63, 32, 16, true>(raw, bid - NB1, p1, Wx2, Wh2, b2, hs2, c2, p2, t2);
    } else if (bid < NB1 + NB2 + NB3) {
        if (t3 >= 0)
            lstm_impl<8, 12, 2, 31, 31, 32, 8, true>(raw, bid - NB1 - NB2, p2, Wx3, Wh3, b3, hs3, c3, p3, t3);
    } else {
        if (t4 >= 0)
            lstm_impl<12, 16, 2, 15, 15, 16, 13, true>(raw, bid - NB1 - NB2 - NB3, p3, Wx4, Wh4, b4, hs4, c4, p4, t4);
    }
}

__global__ void dense_k(const float* __restrict__ xf, const float* __restrict__ Wd,
                        const float* __restrict__ bd, float* __restrict__ logits)
{
    const int FLAT = 18816, NC = 50;
    int b = blockIdx.x, k = blockIdx.y;
    float s = 0.0f;
    for (int j = threadIdx.x; j < FLAT; j += blockDim.x)
        s += xf[(size_t)b * FLAT + j] * __ldg(&Wd[(size_t)j * NC + k]);
    __shared__ float red[128];
    red[threadIdx.x] = s;
    __syncthreads();
    for (int off = 64; off > 0; off >>= 1) {
        if (threadIdx.x < off) red[threadIdx.x] += red[threadIdx.x + off];
        __syncthreads();
    }
    if (threadIdx.x == 0) logits[b * NC + k] = red[0] + __ldg(&bd[k]);
}

__global__ void softmax_k(const float* __restrict__ logits, float* __restrict__ out)
{
    const int NC = 50;
    int b = blockIdx.x, t = threadIdx.x;
    __shared__ float s[64];
    float v = (t < NC) ? logits[b * NC + t] : -INFINITY;
    s[t] = v; __syncthreads();
    for (int off = 32; off > 0; off >>= 1) {
        if (t < off) s[t] = fmaxf(s[t], s[t + off]);
        __syncthreads();
    }
    float m = s[0]; __syncthreads();
    float e = (t < NC) ? expf(v - m) : 0.0f;
    s[t] = e; __syncthreads();
    for (int off = 32; off > 0; off >>= 1) {
        if (t < off) s[t] += s[t + off];
        __syncthreads();
    }
    float sum = s[0];
    if (t < NC) out[b * NC + t] = e / sum;
}

template <typename Sym>
static float* symaddr(const Sym& s) {
    void* p = nullptr;
    cudaGetSymbolAddress(&p, s);
    return (float*)p;
}

extern "C" void kernel_launch(void* const* d_in, const int* in_sizes, int n_in,
                              void* d_out, int out_size)
{
    const float* x   = (const float*)d_in[0];
    const float* Wx1 = (const float*)d_in[1];
    const float* Wh1 = (const float*)d_in[2];
    const float* b1  = (const float*)d_in[3];
    const float* Wx2 = (const float*)d_in[4];
    const float* Wh2 = (const float*)d_in[5];
    const float* b2  = (const float*)d_in[6];
    const float* Wx3 = (const float*)d_in[7];
    const float* Wh3 = (const float*)d_in[8];
    const float* b3  = (const float*)d_in[9];
    const float* Wx4 = (const float*)d_in[10];
    const float* Wh4 = (const float*)d_in[11];
    const float* b4  = (const float*)d_in[12];
    const float* Wd  = (const float*)d_in[13];
    const float* bd  = (const float*)d_in[14];
    float* out = (float*)d_out;

    float* hs1 = symaddr(g_hs1); float* c1 = symaddr(g_c1); float* p1 = symaddr(g_p1);
    float* hs2 = symaddr(g_hs2); float* c2 = symaddr(g_c2); float* p2 = symaddr(g_p2);
    float* hs3 = symaddr(g_hs3); float* c3 = symaddr(g_c3); float* p3 = symaddr(g_p3);
    float* hs4 = symaddr(g_hs4); float* c4 = symaddr(g_c4); float* p4 = symaddr(g_p4);
    float* logits = symaddr(g_logits);

    for (int s = 0; s < Tv + 3; s++) {
        int t1 = (s < Tv) ? s : -1;
        int t2 = (s - 1 >= 0 && s - 1 < Tv) ? s - 1 : -1;
        int t3 = (s - 2 >= 0 && s - 2 < Tv) ? s - 2 : -1;
        int t4 = (s - 3 >= 0 && s - 3 < Tv) ? s - 3 : -1;

        cudaLaunchConfig_t cfg = {};
        cfg.gridDim = dim3(NBT);
        cfg.blockDim = dim3(256);
        cfg.dynamicSmemBytes = 0;
        cfg.stream = 0;
        cudaLaunchAttribute attr[1];
        attr[0].id = cudaLaunchAttributeProgrammaticStreamSerialization;
        attr[0].val.programmaticStreamSerializationAllowed = 1;
        cfg.attrs = attr;
        cfg.numAttrs = 1;

        cudaError_t e = cudaLaunchKernelEx(&cfg, mega_step, x,
                                           Wx1, Wh1, b1, Wx2, Wh2, b2,
                                           Wx3, Wh3, b3, Wx4, Wh4, b4,
                                           hs1, c1, p1, hs2, c2, p2,
                                           hs3, c3, p3, hs4, c4, p4,
                                           t1, t2, t3, t4);
        if (e != cudaSuccess) {
            cudaGetLastError();
            mega_step<<<NBT, 256>>>(x,
                                    Wx1, Wh1, b1, Wx2, Wh2, b2,
                                    Wx3, Wh3, b3, Wx4, Wh4, b4,
                                    hs1, c1, p1, hs2, c2, p2,
                                    hs3, c3, p3, hs4, c4, p4,
                                    t1, t2, t3, t4);
        }
    }

    dim3 dgrid(Bv, 50);
    dense_k<<<dgrid, 128>>>(p4, Wd, bd, logits);
    softmax_k<<<Bv, 64>>>(logits, out);
}